// round 12
// baseline (speedup 1.0000x reference)
#include <cuda_runtime.h>

// VectorQuantizer: inputs [32, 64, 64, 64] fp32 NCHW (C = D = 64), embedding [512, 64] fp32.
// Bit-exact replication of the reference fp32 arithmetic:
//   A   = sum_d fl(x_d * x_d)            (sequential mul-then-add chain, ascending d)
//   e2k = sum_d fl(e_d * e_d)            (sequential mul-then-add chain, ascending d)
//   s_k = FMA-chain_d (x_d * e_dk)       (ascending d, single accumulator per code)
//   dist_k = fl( fl(A + e2k) + fl(-2*s_k) )
//   argmin: first-occurrence. dist > 0 -> fp32 bits monotone: REDUX.MIN.U32 on bits,
//           descending-k equality scan per lane, REDUX.MIN.U32 on candidate k.
//   out = fl(x + fl(q - x))              (exact straight-through-estimator rounding)
//
// Layout: lanes own CODES (stride-1 LDS.128 codebook), pixels staged in smem as
// PRE-PACKED f32x2 duplicate pairs (no pack MOVs in the hot loop), P=8 pixels per
// warp-block share every codebook load.

#define NUM_CODES 512
#define DIMS      64
#define TPB       256
#define NPIX      (32 * 64 * 64)          // 131072 pixels
#define IMG_STRIDE (64 * 4096)
#define TILE      128                      // pixels per CTA pass
#define NTILES    (NPIX / TILE)            // 1024
#define GRID      152

// smem layout (float units)
#define ES_OFF   0                          // Es[d][k]        64*512 f
#define E2_OFF   (DIMS * NUM_CODES)         // e2s[k]          512 f
#define XS_OFF   (E2_OFF + NUM_CODES)       // xs_dup[d][px]   64*128 ull (=16384 f)
#define AS_OFF   (XS_OFF + DIMS * TILE * 2) // A[px]           128 f
#define WIN_OFF  (AS_OFF + TILE)            // win[px]         128 u32
#define SMEM_FLOATS (WIN_OFF + TILE)
#define SMEM_BYTES  (SMEM_FLOATS * 4)       // 199680 bytes

typedef unsigned long long ull;

__device__ __forceinline__ ull ffma2(ull a, ull b, ull c) {
    ull d;
    asm("fma.rn.f32x2 %0, %1, %2, %3;" : "=l"(d) : "l"(a), "l"(b), "l"(c));
    return d;
}
__device__ __forceinline__ ull fadd2(ull a, ull b) {
    ull d;
    asm("add.rn.f32x2 %0, %1, %2;" : "=l"(d) : "l"(a), "l"(b));
    return d;
}
__device__ __forceinline__ ull fmul2(ull a, ull b) {
    ull d;
    asm("mul.rn.f32x2 %0, %1, %2;" : "=l"(d) : "l"(a), "l"(b));
    return d;
}
__device__ __forceinline__ ull pack2(float x) {
    ull r;
    asm("mov.b64 %0, {%1, %1};" : "=l"(r) : "f"(x));
    return r;
}
__device__ __forceinline__ void unpack2(ull v, float& lo, float& hi) {
    asm("mov.b64 {%0, %1}, %2;" : "=f"(lo), "=f"(hi) : "l"(v));
}

__global__ __launch_bounds__(TPB, 1)
void vq_kernel(const float* __restrict__ in,
               const float* __restrict__ emb,
               float* __restrict__ out) {
    extern __shared__ float smem[];
    float* Es  = smem + ES_OFF;             // transposed codebook [DIMS][NUM_CODES]
    float* e2s = smem + E2_OFF;             // ||e_k||^2
    ull*   xsd = reinterpret_cast<ull*>(smem + XS_OFF);   // x tile, duplicated pairs
    float* As  = smem + AS_OFF;             // ||x||^2 per pixel
    unsigned* win = reinterpret_cast<unsigned*>(smem + WIN_OFF);

    const int tid  = threadIdx.x;
    const int lane = tid & 31;
    const int w    = tid >> 5;

    // ---- Stage codebook into smem, transposed, + sequential-chain squared norms ----
    #pragma unroll
    for (int kk = 0; kk < 2; ++kk) {
        const int k = tid + kk * TPB;
        const float4* row = reinterpret_cast<const float4*>(emb + k * DIMS);
        float s = 0.0f;
        #pragma unroll
        for (int j = 0; j < DIMS / 4; ++j) {
            float4 v = row[j];
            Es[(4 * j + 0) * NUM_CODES + k] = v.x;
            Es[(4 * j + 1) * NUM_CODES + k] = v.y;
            Es[(4 * j + 2) * NUM_CODES + k] = v.z;
            Es[(4 * j + 3) * NUM_CODES + k] = v.w;
            s = __fadd_rn(s, __fmul_rn(v.x, v.x));
            s = __fadd_rn(s, __fmul_rn(v.y, v.y));
            s = __fadd_rn(s, __fmul_rn(v.z, v.z));
            s = __fadd_rn(s, __fmul_rn(v.w, v.w));
        }
        e2s[k] = s;
    }
    __syncthreads();

    const ull neg2 = pack2(-2.0f);

    for (int tile = blockIdx.x; tile < NTILES; tile += GRID) {
        // pixels px = tile*128 + i; (px>>12) constant per tile since 128 | 4096
        const int tileBase = (tile >> 5) * IMG_STRIDE + (tile & 31) * TILE;

        // ---- Stage x tile as duplicated f32x2 pairs; coalesced gmem reads ----
        {
            const int i = tid & 127;
            const int h = tid >> 7;
            const float* px = in + tileBase + i;
            #pragma unroll
            for (int j = 0; j < 32; ++j) {
                const int d = h * 32 + j;
                xsd[d * TILE + i] = pack2(px[(size_t)d << 12]);
            }
        }
        __syncthreads();

        // ---- A = ||x||^2 per pixel: strict sequential chain ascending d ----
        if (tid < TILE) {
            float A = 0.0f;
            #pragma unroll
            for (int d = 0; d < DIMS; ++d) {
                const float v = *reinterpret_cast<const float*>(xsd + d * TILE + tid);
                A = __fadd_rn(A, __fmul_rn(v, v));
            }
            As[tid] = A;
        }
        __syncthreads();

        // ---- Compute: warp w handles px [w*16, w*16+16), in two blocks of P=8 ----
        // lane owns codes k = c*128 + lane*4 + {0..3}, c = 0..3 (16 codes -> 8 f32x2 acc/px)
        #pragma unroll 1
        for (int halfI = 0; halfI < 2; ++halfI) {
            const int p0 = w * 16 + halfI * 8;

            ull acc[8][8];
            #pragma unroll
            for (int p = 0; p < 8; ++p)
                #pragma unroll
                for (int j = 0; j < 8; ++j) acc[p][j] = 0ull;

            #pragma unroll 4
            for (int d = 0; d < DIMS; ++d) {
                // x: 4 broadcast LDS.128, each carrying 2 pre-packed pixels
                const ulonglong2* xrow =
                    reinterpret_cast<const ulonglong2*>(xsd + d * TILE + p0);
                const ulonglong2 X0 = xrow[0];
                const ulonglong2 X1 = xrow[1];
                const ulonglong2 X2 = xrow[2];
                const ulonglong2 X3 = xrow[3];

                const float* erow = Es + d * NUM_CODES + lane * 4;
                const ulonglong2 E0 = *reinterpret_cast<const ulonglong2*>(erow);
                const ulonglong2 E1 = *reinterpret_cast<const ulonglong2*>(erow + 128);
                const ulonglong2 E2 = *reinterpret_cast<const ulonglong2*>(erow + 256);
                const ulonglong2 E3 = *reinterpret_cast<const ulonglong2*>(erow + 384);

                ull xq[8];
                xq[0] = X0.x; xq[1] = X0.y; xq[2] = X1.x; xq[3] = X1.y;
                xq[4] = X2.x; xq[5] = X2.y; xq[6] = X3.x; xq[7] = X3.y;

                #pragma unroll
                for (int p = 0; p < 8; ++p) {
                    const ull xp = xq[p];
                    acc[p][0] = ffma2(xp, E0.x, acc[p][0]);
                    acc[p][1] = ffma2(xp, E0.y, acc[p][1]);
                    acc[p][2] = ffma2(xp, E1.x, acc[p][2]);
                    acc[p][3] = ffma2(xp, E1.y, acc[p][3]);
                    acc[p][4] = ffma2(xp, E2.x, acc[p][4]);
                    acc[p][5] = ffma2(xp, E2.y, acc[p][5]);
                    acc[p][6] = ffma2(xp, E3.x, acc[p][6]);
                    acc[p][7] = ffma2(xp, E3.y, acc[p][7]);
                }
            }

            // e2 pairs for this lane's codes (shared across the 8 pixels)
            ull e2p[8];
            {
                const float* e2row = e2s + lane * 4;
                #pragma unroll
                for (int c = 0; c < 4; ++c) {
                    const ulonglong2 t =
                        *reinterpret_cast<const ulonglong2*>(e2row + c * 128);
                    e2p[2 * c]     = t.x;
                    e2p[2 * c + 1] = t.y;
                }
            }

            // Finalize per pixel: dist = fl( fl(A+e2) + fl(-2*s) ).
            // Argmin: fminf tree -> REDUX.MIN on fp32 bits (dist>0, monotone) ->
            // descending-k equality scan -> REDUX.MIN on candidate k (first occurrence).
            #pragma unroll
            for (int p = 0; p < 8; ++p) {
                const ull Ap = pack2(As[p0 + p]);
                float dl[16];
                #pragma unroll
                for (int j = 0; j < 8; ++j) {
                    const ull dd = fadd2(fadd2(Ap, e2p[j]), fmul2(neg2, acc[p][j]));
                    unpack2(dd, dl[2 * j], dl[2 * j + 1]);
                }
                float t8[8];
                #pragma unroll
                for (int j = 0; j < 8; ++j) t8[j] = fminf(dl[j], dl[j + 8]);
                #pragma unroll
                for (int s = 4; s >= 1; s >>= 1)
                    #pragma unroll
                    for (int j = 0; j < s; ++j) t8[j] = fminf(t8[j], t8[j + s]);

                const unsigned gbits =
                    __reduce_min_sync(0xFFFFFFFFu, __float_as_uint(t8[0]));

                unsigned kc = 0xFFFFFFFFu;
                #pragma unroll
                for (int j = 7; j >= 0; --j) {      // descending k within lane
                    const unsigned kb =
                        (unsigned)((j >> 1) * 128 + lane * 4 + (j & 1) * 2);
                    if (__float_as_uint(dl[2 * j + 1]) == gbits) kc = kb + 1;
                    if (__float_as_uint(dl[2 * j])     == gbits) kc = kb;
                }
                const unsigned kwin = __reduce_min_sync(0xFFFFFFFFu, kc);
                if (lane == 0) win[p0 + p] = kwin;
            }
        }
        __syncthreads();

        // ---- STE write: thread (i, h) writes 32 dims of pixel i, coalesced ----
        {
            const int i = tid & 127;
            const int h = tid >> 7;
            const unsigned k = win[i];
            float* po = out + tileBase + i;
            #pragma unroll
            for (int j = 0; j < 32; ++j) {
                const int d = h * 32 + j;
                const float xv = *reinterpret_cast<const float*>(xsd + d * TILE + i);
                const float qv = Es[d * NUM_CODES + (int)k];
                po[(size_t)d << 12] = __fadd_rn(xv, __fsub_rn(qv, xv));
            }
        }
        __syncthreads();   // protect xsd/win before next tile overwrites
    }
}

extern "C" void kernel_launch(void* const* d_in, const int* in_sizes, int n_in,
                              void* d_out, int out_size) {
    const float* in  = (const float*)d_in[0];   // inputs  [32,64,64,64] fp32
    const float* emb = (const float*)d_in[1];   // embedding [512,64] fp32
    float* out = (float*)d_out;

    cudaFuncSetAttribute(vq_kernel, cudaFuncAttributeMaxDynamicSharedMemorySize, SMEM_BYTES);
    vq_kernel<<<GRID, TPB, SMEM_BYTES>>>(in, emb, out);
}